// round 1
// baseline (speedup 1.0000x reference)
#include <cuda_runtime.h>

// Problem constants
#define T_LEN   1024
#define NSTEP   1023      // T-1 outputs
#define B_SZ    8192
#define FORGET_K 0.95f    // 1 - FORGET

typedef unsigned long long ull;

// ---------------- f32x2 packed-math helpers (sm_100+) ----------------
__device__ __forceinline__ void ffma2(ull& d, ull a, ull b) {
    asm("fma.rn.f32x2 %0, %1, %2, %0;" : "+l"(d) : "l"(a), "l"(b));
}
__device__ __forceinline__ ull pack2(float x, float y) {
    ull r; asm("mov.b64 %0, {%1, %2};" : "=l"(r) : "f"(x), "f"(y)); return r;
}
__device__ __forceinline__ float2 unpack2(ull v) {
    float2 r; asm("mov.b64 {%0, %1}, %2;" : "=f"(r.x), "=f"(r.y) : "l"(v)); return r;
}

// Accurate fast tanh: tanh(x) = 1 - 2/(e^{2x}+1), via MUFU.EX2 + MUFU.RCP (~1e-6 err)
__device__ __forceinline__ float tanh_fast(float x) {
    float e, r;
    asm("ex2.approx.f32 %0, %1;" : "=f"(e) : "f"(x * 2.8853900817779268f)); // 2*log2(e)
    asm("rcp.approx.f32 %0, %1;" : "=f"(r) : "f"(e + 1.0f));
    return fmaf(-2.0f, r, 1.0f);
}

__global__ void __launch_bounds__(32)
memann_kernel(const int*   __restrict__ actions,   // [B, T] int32
              const float* __restrict__ rewards,   // [B, T]
              const float* __restrict__ w_r1,      // [32, 33]
              const float* __restrict__ b_r1,      // [32]
              const float* __restrict__ w_r2,      // [1, 32]
              const float* __restrict__ b_r2,      // [1]
              const float* __restrict__ w_a1,      // [32, 36]
              const float* __restrict__ b_a1,      // [32]
              const float* __restrict__ w_a2,      // [4, 32]
              const float* __restrict__ b_a2,      // [4]
              float*       __restrict__ out)       // [B, T-1, 4]
{
    // ---- shared layout (per 1-warp CTA handling 8 batch elements) ----
    __shared__ __align__(16) float wrT[32][32];   // wrT[j][i] = w_r1[i][1+j]
    __shared__ __align__(16) float waT[32][32];   // waT[j][i] = w_a1[i][4+j]
    __shared__ __align__(16) float colb[4][32];   // w_a1[i][a] + b_a1[i]
    __shared__ __align__(16) float bR[32];
    __shared__ __align__(16) float wc0[32];       // w_r1[i][0]
    __shared__ __align__(16) float wr2s[32];
    __shared__ __align__(16) float wa2s[32][4];   // wa2s[i][k] = w_a2[k][i]
    // state, value-duplicated pairs {v,v}; stride 34 keeps 16B align + no bank conflicts
    __shared__ __align__(16) ull srd[8][34];
    __shared__ __align__(16) ull sad[8][34];

    const int lane  = threadIdx.x;
    const int g     = lane >> 2;    // element group within warp (0..7)
    const int ll    = lane & 3;     // lane within group (0..3)
    const int rbase = ll * 8;       // this lane's 8 output rows

    // ---- one-time weight staging ----
    #pragma unroll
    for (int idx = lane; idx < 1024; idx += 32) {
        int i = idx & 31, j = idx >> 5;
        wrT[j][i] = w_r1[i * 33 + 1 + j];
        waT[j][i] = w_a1[i * 36 + 4 + j];
    }
    #pragma unroll
    for (int idx = lane; idx < 128; idx += 32) {
        int a = idx >> 5, i = idx & 31;
        colb[a][i] = w_a1[i * 36 + a] + b_a1[i];
        int i2 = idx >> 2, k = idx & 3;
        wa2s[i2][k] = w_a2[k * 32 + i2];
    }
    bR[lane]   = b_r1[lane];
    wc0[lane]  = w_r1[lane * 33];
    wr2s[lane] = w_r2[lane];
    #pragma unroll
    for (int idx = lane; idx < 8 * 34; idx += 32) {
        (&srd[0][0])[idx] = 0ull;
        (&sad[0][0])[idx] = 0ull;
    }
    const float br2c  = b_r2[0];
    const float cbias = b_a2[ll];
    __syncthreads();

    // ---- register caches (constant across steps) ----
    ull bR2[4], wc02[4], wr22[4];
    #pragma unroll
    for (int m = 0; m < 4; m++) {
        bR2[m]  = pack2(bR[rbase + 2 * m],   bR[rbase + 2 * m + 1]);
        wc02[m] = pack2(wc0[rbase + 2 * m],  wc0[rbase + 2 * m + 1]);
        wr22[m] = pack2(wr2s[rbase + 2 * m], wr2s[rbase + 2 * m + 1]);
    }

    const long long b = (long long)blockIdx.x * 8 + g;
    const float* rrow = rewards + b * T_LEN;
    const int*   arow = actions + b * T_LEN;
    float*       orow = out + b * (long long)(NSTEP * 4);

    float q = 0.0f;   // lane ll's q component (Q_INIT = 0)

    // ---- one timestep ----
    auto step = [&](int t, float r, int a) {
        ull racc[4], aacc[4];
        // reward-module init: b_r1 + w_r1[:,0]*r
        ull rdup = pack2(r, r);
        #pragma unroll
        for (int m = 0; m < 4; m++) { racc[m] = bR2[m]; ffma2(racc[m], wc02[m], rdup); }
        // action-module init: b_a1 + w_a1[:, a]
        {
            const ulonglong2* cp = reinterpret_cast<const ulonglong2*>(&colb[a][rbase]);
            ulonglong2 c0 = cp[0], c1 = cp[1];
            aacc[0] = c0.x; aacc[1] = c0.y; aacc[2] = c1.x; aacc[3] = c1.y;
        }
        // reward recurrence: racc += W_r1[:,1:] @ sr
        #pragma unroll
        for (int j = 0; j < 32; j++) {
            ull v = srd[g][j];
            ulonglong2 w0 = *reinterpret_cast<const ulonglong2*>(&wrT[j][rbase]);
            ulonglong2 w1 = *reinterpret_cast<const ulonglong2*>(&wrT[j][rbase + 4]);
            ffma2(racc[0], w0.x, v);
            ffma2(racc[1], w0.y, v);
            ffma2(racc[2], w1.x, v);
            ffma2(racc[3], w1.y, v);
        }
        // action recurrence: aacc += W_a1[:,4:] @ sa
        #pragma unroll
        for (int j = 0; j < 32; j++) {
            ull v = sad[g][j];
            ulonglong2 w0 = *reinterpret_cast<const ulonglong2*>(&waT[j][rbase]);
            ulonglong2 w1 = *reinterpret_cast<const ulonglong2*>(&waT[j][rbase + 4]);
            ffma2(aacc[0], w0.x, v);
            ffma2(aacc[1], w0.y, v);
            ffma2(aacc[2], w1.x, v);
            ffma2(aacc[3], w1.y, v);
        }
        // tanh
        float2 tr[4], ta[4];
        #pragma unroll
        for (int m = 0; m < 4; m++) {
            float2 u = unpack2(racc[m]);
            tr[m].x = tanh_fast(u.x); tr[m].y = tanh_fast(u.y);
            float2 w = unpack2(aacc[m]);
            ta[m].x = tanh_fast(w.x); ta[m].y = tanh_fast(w.y);
        }
        // q_new = w_r2 . sr_t + b_r2 (4-lane butterfly reduce)
        ull qa = 0ull;
        #pragma unroll
        for (int m = 0; m < 4; m++) ffma2(qa, wr22[m], pack2(tr[m].x, tr[m].y));
        float2 qf = unpack2(qa);
        float qp = qf.x + qf.y;
        qp += __shfl_xor_sync(0xFFFFFFFFu, qp, 1);
        qp += __shfl_xor_sync(0xFFFFFFFFu, qp, 2);
        const float q_new = qp + br2c;

        __syncthreads();   // all reads of old state done

        // write new state (duplicated pairs); keep sa dups for c_t
        ull sadup[8];
        #pragma unroll
        for (int m = 0; m < 4; m++) {
            ull d0 = pack2(tr[m].x, tr[m].x);
            ull d1 = pack2(tr[m].y, tr[m].y);
            *reinterpret_cast<ulonglong2*>(&srd[g][rbase + 2 * m]) = make_ulonglong2(d0, d1);
            sadup[2 * m]     = pack2(ta[m].x, ta[m].x);
            sadup[2 * m + 1] = pack2(ta[m].y, ta[m].y);
            *reinterpret_cast<ulonglong2*>(&sad[g][rbase + 2 * m]) =
                make_ulonglong2(sadup[2 * m], sadup[2 * m + 1]);
        }
        // c_t = W_a2 @ sa_t (partial over this lane's 8 rows, then 4-lane reduce)
        ull c01 = 0ull, c23 = 0ull;
        #pragma unroll
        for (int s = 0; s < 8; s++) {
            ulonglong2 wv = *reinterpret_cast<const ulonglong2*>(&wa2s[rbase + s][0]);
            ffma2(c01, wv.x, sadup[s]);
            ffma2(c23, wv.y, sadup[s]);
        }
        float2 cA = unpack2(c01), cB = unpack2(c23);
        #pragma unroll
        for (int ofs = 1; ofs <= 2; ofs <<= 1) {
            cA.x += __shfl_xor_sync(0xFFFFFFFFu, cA.x, ofs);
            cA.y += __shfl_xor_sync(0xFFFFFFFFu, cA.y, ofs);
            cB.x += __shfl_xor_sync(0xFFFFFFFFu, cB.x, ofs);
            cB.y += __shfl_xor_sync(0xFFFFFFFFu, cB.y, ofs);
        }
        const float cm = (ll == 0) ? cA.x : (ll == 1) ? cA.y : (ll == 2) ? cB.x : cB.y;

        // q update + logits
        q = (a == ll) ? q_new : q * FORGET_K;
        if (t < NSTEP) orow[t * 4 + ll] = q + cm + cbias;

        __syncthreads();   // new state visible before next step's reads
    };

    // ---- main time loop, 2 steps per block with input prefetch ----
    float2 rv = *reinterpret_cast<const float2*>(rrow);
    int2   av = *reinterpret_cast<const int2*>(arow);
    for (int t0 = 0; t0 < T_LEN; t0 += 2) {
        float2 rvn = make_float2(0.f, 0.f);
        int2   avn = make_int2(0, 0);
        if (t0 + 2 < T_LEN) {
            rvn = *reinterpret_cast<const float2*>(rrow + t0 + 2);
            avn = *reinterpret_cast<const int2*>(arow + t0 + 2);
        }
        step(t0,     rv.x, av.x);
        step(t0 + 1, rv.y, av.y);
        rv = rvn; av = avn;
    }
}

extern "C" void kernel_launch(void* const* d_in, const int* in_sizes, int n_in,
                              void* d_out, int out_size) {
    (void)in_sizes; (void)n_in; (void)out_size;
    memann_kernel<<<B_SZ / 8, 32>>>(
        (const int*)  d_in[0],   // actions
        (const float*)d_in[1],   // rewards
        (const float*)d_in[2],   // w_r1
        (const float*)d_in[3],   // b_r1
        (const float*)d_in[4],   // w_r2
        (const float*)d_in[5],   // b_r2
        (const float*)d_in[6],   // w_a1
        (const float*)d_in[7],   // b_a1
        (const float*)d_in[8],   // w_a2
        (const float*)d_in[9],   // b_a2
        (float*)d_out);
}